// round 4
// baseline (speedup 1.0000x reference)
#include <cuda_runtime.h>
#include <cuda_bf16.h>
#include <math.h>
#include <cstdint>

// ---------------------------------------------------------------------------
// LSTMCell, B=8192, In=H=1024.
//   V = [x|h] @ [w_ih|w_hh]^T            (8192x2048 @ 2048x4096^T, NT)
//   gates = LN_per_gate(V + b_ih); f+=1
//   new_c = LN_c(c*sig(f) + sig(i)*tanh(g)); new_h = tanh(new_c)*sig(o)
//
// GEMM: split-bf16 (a = a_hi + a_lo; 3 MMAs hi*hi + hi*lo + lo*hi) on
// mma.sync.m16n8k16 (sm_80 PTX; tcgen05 unavailable: harness emits
// compute_100 PTX).  rel_err ~1e-5.
//
// NT GEMM with both operands K-contiguous => BOTH A and B fragments use
// NON-transposed ldmatrix (fixed vs previous round's .trans on B).
// ---------------------------------------------------------------------------

#define Bsz   8192
#define Hsz   1024
#define Nsz   4096
#define GK    2048          // packed K = In + H
#define EPS   1e-6f

#define TM    128
#define TN    128
#define BK    64            // K per smem chunk (64 bf16 = 128 B row, SW128)
#define NCHUNK (GK / BK)    // 32

// smem: per stage 4 tiles (Ahi, Alo, Bhi, Blo), each 128 rows x 128 B = 16 KB
#define TILE_B   16384
#define STAGE_B  (4 * TILE_B)
#define DYN_SMEM (2 * STAGE_B)   // 128 KB

// ---- scratch (static device globals; allocation-free) ----
__device__ __nv_bfloat16 g_a_hi[(size_t)Bsz * GK];   // [x|h] hi
__device__ __nv_bfloat16 g_a_lo[(size_t)Bsz * GK];
__device__ __nv_bfloat16 g_b_hi[(size_t)Nsz * GK];   // [w_ih|w_hh] hi
__device__ __nv_bfloat16 g_b_lo[(size_t)Nsz * GK];
__device__ float         g_v[(size_t)Bsz * Nsz];     // pre-activation gates

// ---------------------------------------------------------------------------
// helpers
// ---------------------------------------------------------------------------
__device__ __forceinline__ uint32_t smem_u32(const void* p) {
    uint32_t a;
    asm("{ .reg .u64 t; cvta.to.shared.u64 t, %1; cvt.u32.u64 %0, t; }"
        : "=r"(a) : "l"(p));
    return a;
}
__device__ __forceinline__ uint32_t sw128(uint32_t off) {
    return off ^ ((off >> 3) & 0x70);
}
__device__ __forceinline__ void cp16(uint32_t saddr, const void* gaddr) {
    asm volatile("cp.async.cg.shared.global [%0], [%1], 16;"
                 :: "r"(saddr), "l"(gaddr));
}
__device__ __forceinline__ void cp_commit() {
    asm volatile("cp.async.commit_group;" ::: "memory");
}
template <int N>
__device__ __forceinline__ void cp_wait() {
    asm volatile("cp.async.wait_group %0;" :: "n"(N) : "memory");
}
__device__ __forceinline__ void ldsm4(uint32_t& r0, uint32_t& r1,
                                      uint32_t& r2, uint32_t& r3, uint32_t a) {
    asm volatile("ldmatrix.sync.aligned.m8n8.x4.shared.b16 {%0,%1,%2,%3}, [%4];"
                 : "=r"(r0), "=r"(r1), "=r"(r2), "=r"(r3) : "r"(a));
}
__device__ __forceinline__ void mma16816(float* c, const uint32_t* a,
                                         const uint32_t* b) {
    asm volatile(
        "mma.sync.aligned.m16n8k16.row.col.f32.bf16.bf16.f32 "
        "{%0,%1,%2,%3}, {%4,%5,%6,%7}, {%8,%9}, {%0,%1,%2,%3};"
        : "+f"(c[0]), "+f"(c[1]), "+f"(c[2]), "+f"(c[3])
        : "r"(a[0]), "r"(a[1]), "r"(a[2]), "r"(a[3]), "r"(b[0]), "r"(b[1]));
}

// ---------------------------------------------------------------------------
// Kernel 1: fp32 -> split bf16 (hi + lo) into packed [.,2048] scratch
// ---------------------------------------------------------------------------
__global__ __launch_bounds__(256) void lstm_convert(
    const float* __restrict__ x, const float* __restrict__ h,
    const float* __restrict__ w_ih, const float* __restrict__ w_hh)
{
    const size_t NG_A = (size_t)Bsz * (GK / 4);
    const size_t NG   = NG_A + (size_t)Nsz * (GK / 4);
    size_t g = (size_t)blockIdx.x * blockDim.x + threadIdx.x;
    if (g >= NG) return;

    const float* src;
    __nv_bfloat16 *dhi, *dlo;
    size_t dstoff;
    if (g < NG_A) {
        size_t r = g / (GK / 4);
        int    k = (int)(g % (GK / 4)) * 4;
        src = (k < 1024) ? (x + r * 1024 + k) : (h + r * 1024 + (k - 1024));
        dstoff = r * GK + k;
        dhi = g_a_hi; dlo = g_a_lo;
    } else {
        size_t gb = g - NG_A;
        size_t r = gb / (GK / 4);
        int    k = (int)(gb % (GK / 4)) * 4;
        src = (k < 1024) ? (w_ih + r * 1024 + k) : (w_hh + r * 1024 + (k - 1024));
        dstoff = r * GK + k;
        dhi = g_b_hi; dlo = g_b_lo;
    }

    float4 v = *(const float4*)src;
    float vs[4] = {v.x, v.y, v.z, v.w};
    __nv_bfloat16 hi[4], lo[4];
#pragma unroll
    for (int j = 0; j < 4; j++) {
        hi[j] = __float2bfloat16(vs[j]);
        lo[j] = __float2bfloat16(vs[j] - __bfloat162float(hi[j]));
    }
    *(__nv_bfloat162*)(dhi + dstoff)     = __nv_bfloat162(hi[0], hi[1]);
    *(__nv_bfloat162*)(dhi + dstoff + 2) = __nv_bfloat162(hi[2], hi[3]);
    *(__nv_bfloat162*)(dlo + dstoff)     = __nv_bfloat162(lo[0], lo[1]);
    *(__nv_bfloat162*)(dlo + dstoff + 2) = __nv_bfloat162(lo[2], lo[3]);
}

// ---------------------------------------------------------------------------
// Kernel 2: split-bf16 GEMM on mma.sync.  Tile 128x128xBK64, 256 threads,
// 8 warps (2 M x 4 N), warp tile 64x32, double-buffered cp.async.
// ---------------------------------------------------------------------------
__global__ __launch_bounds__(256, 1) void lstm_gemm_mma()
{
    extern __shared__ char smem[];
    const uint32_t sbase = smem_u32(smem);

    const int tid  = threadIdx.x;
    const int lane = tid & 31;
    const int wid  = tid >> 5;
    const int wm   = wid >> 2;          // 0..1  (M)
    const int wn   = wid & 3;           // 0..3  (N)
    const int m0   = blockIdx.y * TM;
    const int n0   = blockIdx.x * TN;

    // gmem row bases for this thread's cp.async slice
    // each stage: 4 tiles x 1024 16B-chunks; thread does 4 chunks per tile.
    int crow[4], cchk[4];
    uint32_t csw[4];
#pragma unroll
    for (int i = 0; i < 4; i++) {
        int e = tid + 256 * i;
        crow[i] = e >> 3;               // 0..127
        cchk[i] = e & 7;                // 16B chunk in row
        uint32_t off = (uint32_t)crow[i] * 128u + (uint32_t)cchk[i] * 16u;
        csw[i] = sw128(off);
    }

    auto loadChunk = [&](int ch, int buf) {
        const int kk = ch * BK;
        const uint32_t st = sbase + buf * STAGE_B;
#pragma unroll
        for (int i = 0; i < 4; i++) {
            const size_t ga = (size_t)(m0 + crow[i]) * GK + kk + cchk[i] * 8;
            const size_t gb = (size_t)(n0 + crow[i]) * GK + kk + cchk[i] * 8;
            cp16(st + 0 * TILE_B + csw[i], g_a_hi + ga);
            cp16(st + 1 * TILE_B + csw[i], g_a_lo + ga);
            cp16(st + 2 * TILE_B + csw[i], g_b_hi + gb);
            cp16(st + 3 * TILE_B + csw[i], g_b_lo + gb);
        }
        cp_commit();
    };

    float acc[4][4][4];
#pragma unroll
    for (int mi = 0; mi < 4; mi++)
#pragma unroll
        for (int ni = 0; ni < 4; ni++)
#pragma unroll
            for (int j = 0; j < 4; j++) acc[mi][ni][j] = 0.0f;

    // ldmatrix lane addressing (offsets within a tile)
    // A (m16k16 per ldsm4): lanes 0-7 rows 0-7 k-blk0; 8-15 rows 8-15 blk0;
    //                       16-23 rows 0-7 blk1; 24-31 rows 8-15 blk1.
    const int arow = wm * 64 + (lane & 15);               // + mi*16
    const uint32_t acolb = (uint32_t)((lane >> 4) << 4);  // +16B if lane>=16
    // B (n16k16 per ldsm4): lanes 0-7 n0-7 kblk0; 8-15 n0-7 kblk1;
    //                       16-23 n8-15 kblk0; 24-31 n8-15 kblk1.
    //   -> regs r0,r1 = b0,b1 for n0-7; r2,r3 = b0,b1 for n8-15.
    const int brow = wn * 32 + ((lane >> 4) << 3) + (lane & 7);  // + nb*16
    const uint32_t bcolb = (uint32_t)(((lane >> 3) & 1) << 4);

    loadChunk(0, 0);

    int buf = 0;
    for (int ch = 0; ch < NCHUNK; ch++) {
        if (ch + 1 < NCHUNK) loadChunk(ch + 1, buf ^ 1);

        if (ch + 1 < NCHUNK) cp_wait<1>(); else cp_wait<0>();
        __syncthreads();

        const uint32_t st   = sbase + buf * STAGE_B;
        const uint32_t sAhi = st;
        const uint32_t sAlo = st + TILE_B;
        const uint32_t sBhi = st + 2 * TILE_B;
        const uint32_t sBlo = st + 3 * TILE_B;

#pragma unroll
        for (int ks = 0; ks < 4; ks++) {
            const uint32_t kb = (uint32_t)(ks * 32);   // k0 bytes

            uint32_t Ah[4][4], Al[4][4];
#pragma unroll
            for (int mi = 0; mi < 4; mi++) {
                uint32_t off = (uint32_t)(arow + mi * 16) * 128u + kb + acolb;
                uint32_t sw  = sw128(off);
                ldsm4(Ah[mi][0], Ah[mi][1], Ah[mi][2], Ah[mi][3], sAhi + sw);
                ldsm4(Al[mi][0], Al[mi][1], Al[mi][2], Al[mi][3], sAlo + sw);
            }
            uint32_t Bh[2][4], Bl[2][4];
#pragma unroll
            for (int nb = 0; nb < 2; nb++) {
                uint32_t off = (uint32_t)(brow + nb * 16) * 128u + kb + bcolb;
                uint32_t sw  = sw128(off);
                ldsm4(Bh[nb][0], Bh[nb][1], Bh[nb][2], Bh[nb][3], sBhi + sw);
                ldsm4(Bl[nb][0], Bl[nb][1], Bl[nb][2], Bl[nb][3], sBlo + sw);
            }

#pragma unroll
            for (int mi = 0; mi < 4; mi++)
#pragma unroll
                for (int ni = 0; ni < 4; ni++) {
                    const int nb = ni >> 1, j = ni & 1;
                    uint32_t bh[2] = {Bh[nb][2 * j], Bh[nb][2 * j + 1]};
                    uint32_t bl[2] = {Bl[nb][2 * j], Bl[nb][2 * j + 1]};
                    mma16816(acc[mi][ni], Ah[mi], bh);   // hi*hi
                    mma16816(acc[mi][ni], Ah[mi], bl);   // hi*lo
                    mma16816(acc[mi][ni], Al[mi], bh);   // lo*hi
                }
        }
        __syncthreads();
        buf ^= 1;
    }

    // write V  (mma D fragment: d0,d1 = row t/4, cols (t%4)*2,+1; d2,d3 = row+8)
#pragma unroll
    for (int mi = 0; mi < 4; mi++) {
        const int r0 = m0 + wm * 64 + mi * 16 + (lane >> 2);
#pragma unroll
        for (int ni = 0; ni < 4; ni++) {
            const int cc = n0 + wn * 32 + ni * 8 + (lane & 3) * 2;
            float2 v0 = {acc[mi][ni][0], acc[mi][ni][1]};
            float2 v1 = {acc[mi][ni][2], acc[mi][ni][3]};
            *(float2*)&g_v[(size_t)r0 * Nsz + cc]       = v0;
            *(float2*)&g_v[(size_t)(r0 + 8) * Nsz + cc] = v1;
        }
    }
}

// ---------------------------------------------------------------------------
// Kernel 3: epilogue — per-row gate LN, gate math, cell LN.  1 block/row.
// ---------------------------------------------------------------------------
__device__ __forceinline__ float sigf(float v) { return 1.0f / (1.0f + expf(-v)); }

__global__ __launch_bounds__(256) void lstm_epilogue(
    const float* __restrict__ c,
    const float* __restrict__ b_ih,
    const float* __restrict__ gamma_ifgo, const float* __restrict__ beta_ifgo,
    const float* __restrict__ gamma_c,    const float* __restrict__ beta_c,
    float* __restrict__ out)   // [2, B, H]: new_h then new_c
{
    const int b   = blockIdx.x;
    const int tid = threadIdx.x;
    const int col = tid * 4;
    const int lane = tid & 31, wid = tid >> 5;

    const float* vrow = g_v + (size_t)b * Nsz;
    __shared__ float wred[8][8];

    float gv[4][4];
    float s[8];
#pragma unroll
    for (int g = 0; g < 4; g++) {
        float4 t  = *(const float4*)&vrow[g * Hsz + col];
        float4 bb = *(const float4*)&b_ih[g * Hsz + col];
        float v0 = t.x + bb.x, v1 = t.y + bb.y, v2 = t.z + bb.z, v3 = t.w + bb.w;
        gv[g][0] = v0; gv[g][1] = v1; gv[g][2] = v2; gv[g][3] = v3;
        s[2 * g]     = v0 + v1 + v2 + v3;
        s[2 * g + 1] = v0 * v0 + v1 * v1 + v2 * v2 + v3 * v3;
    }

#pragma unroll
    for (int j = 0; j < 8; j++)
#pragma unroll
        for (int off = 16; off > 0; off >>= 1)
            s[j] += __shfl_xor_sync(0xffffffffu, s[j], off);
    if (lane == 0)
#pragma unroll
        for (int j = 0; j < 8; j++) wred[wid][j] = s[j];
    __syncthreads();

    float tot[8];
#pragma unroll
    for (int j = 0; j < 8; j++) {
        float a = 0.0f;
#pragma unroll
        for (int w = 0; w < 8; w++) a += wred[w][j];
        tot[j] = a;
    }

    float ln[4][4];
#pragma unroll
    for (int g = 0; g < 4; g++) {
        float mean = tot[2 * g] * (1.0f / Hsz);
        float var  = (tot[2 * g + 1] - tot[2 * g] * mean) * (1.0f / (Hsz - 1));
        float inv  = 1.0f / (sqrtf(fmaxf(var, 0.0f)) + EPS);
        float4 ga = *(const float4*)&gamma_ifgo[g * Hsz + col];
        float4 be = *(const float4*)&beta_ifgo[g * Hsz + col];
        float gaa[4] = {ga.x, ga.y, ga.z, ga.w};
        float bea[4] = {be.x, be.y, be.z, be.w};
#pragma unroll
        for (int j = 0; j < 4; j++)
            ln[g][j] = gaa[j] * (gv[g][j] - mean) * inv + bea[j];
    }

    float4 cv4 = *(const float4*)&c[(size_t)b * Hsz + col];
    float cva[4] = {cv4.x, cv4.y, cv4.z, cv4.w};
    float nc[4];
    float s2 = 0.0f, s3 = 0.0f;
#pragma unroll
    for (int j = 0; j < 4; j++) {
        float fi = ln[1][j] + 1.0f;
        float v  = cva[j] * sigf(fi) + sigf(ln[0][j]) * tanhf(ln[2][j]);
        nc[j] = v;
        s2 += v;
        s3 += v * v;
    }

    __syncthreads();
#pragma unroll
    for (int off = 16; off > 0; off >>= 1) {
        s2 += __shfl_xor_sync(0xffffffffu, s2, off);
        s3 += __shfl_xor_sync(0xffffffffu, s3, off);
    }
    if (lane == 0) { wred[wid][0] = s2; wred[wid][1] = s3; }
    __syncthreads();
    float t2 = 0.0f, t3 = 0.0f;
#pragma unroll
    for (int w = 0; w < 8; w++) { t2 += wred[w][0]; t3 += wred[w][1]; }

    float mean2 = t2 * (1.0f / Hsz);
    float var2  = (t3 - t2 * mean2) * (1.0f / (Hsz - 1));
    float inv2  = 1.0f / (sqrtf(fmaxf(var2, 0.0f)) + EPS);

    float4 gc4 = *(const float4*)&gamma_c[col];
    float4 bc4 = *(const float4*)&beta_c[col];
    float gca[4] = {gc4.x, gc4.y, gc4.z, gc4.w};
    float bca[4] = {bc4.x, bc4.y, bc4.z, bc4.w};

    float hn[4], cn[4];
#pragma unroll
    for (int j = 0; j < 4; j++) {
        float cl = gca[j] * (nc[j] - mean2) * inv2 + bca[j];
        cn[j] = cl;
        hn[j] = tanhf(cl) * sigf(ln[3][j]);
    }

    float4 ho = {hn[0], hn[1], hn[2], hn[3]};
    float4 co = {cn[0], cn[1], cn[2], cn[3]};
    *(float4*)&out[(size_t)b * Hsz + col]                     = ho;
    *(float4*)&out[(size_t)Bsz * Hsz + (size_t)b * Hsz + col] = co;
}

// ---------------------------------------------------------------------------
// Launch
// ---------------------------------------------------------------------------
extern "C" void kernel_launch(void* const* d_in, const int* in_sizes, int n_in,
                              void* d_out, int out_size)
{
    const float* x          = (const float*)d_in[0];
    const float* h          = (const float*)d_in[1];
    const float* c          = (const float*)d_in[2];
    const float* w_ih       = (const float*)d_in[3];
    const float* b_ih       = (const float*)d_in[4];
    const float* w_hh       = (const float*)d_in[5];
    const float* gamma_ifgo = (const float*)d_in[6];
    const float* beta_ifgo  = (const float*)d_in[7];
    const float* gamma_c    = (const float*)d_in[8];
    const float* beta_c     = (const float*)d_in[9];
    float* out = (float*)d_out;

    // idempotent, called every launch (no static guards)
    cudaFuncSetAttribute(lstm_gemm_mma,
                         cudaFuncAttributeMaxDynamicSharedMemorySize, DYN_SMEM);

    {   // convert: (8192 + 4096) * 512 float4-groups
        size_t groups = ((size_t)Bsz + Nsz) * (GK / 4);
        int blocks = (int)((groups + 255) / 256);
        lstm_convert<<<blocks, 256>>>(x, h, w_ih, w_hh);
    }

    dim3 gemmGrid(Nsz / TN, Bsz / TM);   // (32, 64)
    lstm_gemm_mma<<<gemmGrid, 256, DYN_SMEM>>>();

    lstm_epilogue<<<Bsz, 256>>>(c, b_ih, gamma_ifgo, beta_ifgo,
                                gamma_c, beta_c, out);
}

// round 5
// speedup vs baseline: 1.0080x; 1.0080x over previous
#include <cuda_runtime.h>
#include <cuda_bf16.h>
#include <math.h>
#include <cstdint>

// ---------------------------------------------------------------------------
// LSTMCell, B=8192, In=H=1024.
//   V = [x|h] @ [w_ih|w_hh]^T            (8192x2048 @ 2048x4096^T, NT)
//   gates = LN_per_gate(V + b_ih); f+=1
//   new_c = LN_c(c*sig(f) + sig(i)*tanh(g)); new_h = tanh(new_c)*sig(o)
//
// GEMM: split-bf16 (a = a_hi + a_lo; 3 MMAs hi*hi + hi*lo + lo*hi) on
// mma.sync.m16n8k16.  Round 5: tile 256x128 (was 128x128) -> L2 traffic
// 4 GB -> 3 GB, compute:load per chunk 1.35:1 so cp.async actually hides.
// ---------------------------------------------------------------------------

#define Bsz   8192
#define Hsz   1024
#define Nsz   4096
#define GK    2048          // packed K = In + H
#define EPS   1e-6f

#define TM    256
#define TN    128
#define BK    64            // K per smem chunk (64 bf16 = 128 B row, SW128)
#define NCHUNK (GK / BK)    // 32

// per stage: Ahi/Alo 256x128B = 32 KB each, Bhi/Blo 128x128B = 16 KB each
#define TILE_A_B 32768
#define TILE_B_B 16384
#define STAGE_B  (2 * TILE_A_B + 2 * TILE_B_B)   // 96 KB
#define DYN_SMEM (2 * STAGE_B)                    // 192 KB

// ---- scratch (static device globals; allocation-free) ----
__device__ __nv_bfloat16 g_a_hi[(size_t)Bsz * GK];   // [x|h] hi
__device__ __nv_bfloat16 g_a_lo[(size_t)Bsz * GK];
__device__ __nv_bfloat16 g_b_hi[(size_t)Nsz * GK];   // [w_ih|w_hh] hi
__device__ __nv_bfloat16 g_b_lo[(size_t)Nsz * GK];
__device__ float         g_v[(size_t)Bsz * Nsz];     // pre-activation gates

// ---------------------------------------------------------------------------
// helpers
// ---------------------------------------------------------------------------
__device__ __forceinline__ uint32_t smem_u32(const void* p) {
    uint32_t a;
    asm("{ .reg .u64 t; cvta.to.shared.u64 t, %1; cvt.u32.u64 %0, t; }"
        : "=r"(a) : "l"(p));
    return a;
}
__device__ __forceinline__ uint32_t sw128(uint32_t off) {
    return off ^ ((off >> 3) & 0x70);
}
__device__ __forceinline__ void cp16(uint32_t saddr, const void* gaddr) {
    asm volatile("cp.async.cg.shared.global [%0], [%1], 16;"
                 :: "r"(saddr), "l"(gaddr));
}
__device__ __forceinline__ void cp_commit() {
    asm volatile("cp.async.commit_group;" ::: "memory");
}
template <int N>
__device__ __forceinline__ void cp_wait() {
    asm volatile("cp.async.wait_group %0;" :: "n"(N) : "memory");
}
__device__ __forceinline__ void ldsm4(uint32_t& r0, uint32_t& r1,
                                      uint32_t& r2, uint32_t& r3, uint32_t a) {
    asm volatile("ldmatrix.sync.aligned.m8n8.x4.shared.b16 {%0,%1,%2,%3}, [%4];"
                 : "=r"(r0), "=r"(r1), "=r"(r2), "=r"(r3) : "r"(a));
}
__device__ __forceinline__ void mma16816(float* c, const uint32_t* a,
                                         const uint32_t* b) {
    asm volatile(
        "mma.sync.aligned.m16n8k16.row.col.f32.bf16.bf16.f32 "
        "{%0,%1,%2,%3}, {%4,%5,%6,%7}, {%8,%9}, {%0,%1,%2,%3};"
        : "+f"(c[0]), "+f"(c[1]), "+f"(c[2]), "+f"(c[3])
        : "r"(a[0]), "r"(a[1]), "r"(a[2]), "r"(a[3]), "r"(b[0]), "r"(b[1]));
}

// ---------------------------------------------------------------------------
// Kernel 1: fp32 -> split bf16 (hi + lo) into packed [.,2048] scratch
// ---------------------------------------------------------------------------
__global__ __launch_bounds__(256) void lstm_convert(
    const float* __restrict__ x, const float* __restrict__ h,
    const float* __restrict__ w_ih, const float* __restrict__ w_hh)
{
    const size_t NG_A = (size_t)Bsz * (GK / 4);
    const size_t NG   = NG_A + (size_t)Nsz * (GK / 4);
    size_t g = (size_t)blockIdx.x * blockDim.x + threadIdx.x;
    if (g >= NG) return;

    const float* src;
    __nv_bfloat16 *dhi, *dlo;
    size_t dstoff;
    if (g < NG_A) {
        size_t r = g / (GK / 4);
        int    k = (int)(g % (GK / 4)) * 4;
        src = (k < 1024) ? (x + r * 1024 + k) : (h + r * 1024 + (k - 1024));
        dstoff = r * GK + k;
        dhi = g_a_hi; dlo = g_a_lo;
    } else {
        size_t gb = g - NG_A;
        size_t r = gb / (GK / 4);
        int    k = (int)(gb % (GK / 4)) * 4;
        src = (k < 1024) ? (w_ih + r * 1024 + k) : (w_hh + r * 1024 + (k - 1024));
        dstoff = r * GK + k;
        dhi = g_b_hi; dlo = g_b_lo;
    }

    float4 v = *(const float4*)src;
    float vs[4] = {v.x, v.y, v.z, v.w};
    __nv_bfloat16 hi[4], lo[4];
#pragma unroll
    for (int j = 0; j < 4; j++) {
        hi[j] = __float2bfloat16(vs[j]);
        lo[j] = __float2bfloat16(vs[j] - __bfloat162float(hi[j]));
    }
    *(__nv_bfloat162*)(dhi + dstoff)     = __nv_bfloat162(hi[0], hi[1]);
    *(__nv_bfloat162*)(dhi + dstoff + 2) = __nv_bfloat162(hi[2], hi[3]);
    *(__nv_bfloat162*)(dlo + dstoff)     = __nv_bfloat162(lo[0], lo[1]);
    *(__nv_bfloat162*)(dlo + dstoff + 2) = __nv_bfloat162(lo[2], lo[3]);
}

// ---------------------------------------------------------------------------
// Kernel 2: split-bf16 GEMM.  Tile 256x128xBK64, 512 threads,
// 16 warps (4 M x 4 N), warp tile 64x32, double-buffered cp.async.
// ---------------------------------------------------------------------------
__global__ __launch_bounds__(512, 1) void lstm_gemm_mma()
{
    extern __shared__ char smem[];
    const uint32_t sbase = smem_u32(smem);

    const int tid  = threadIdx.x;
    const int lane = tid & 31;
    const int wid  = tid >> 5;
    const int wm   = wid >> 2;          // 0..3  (M)
    const int wn   = wid & 3;           // 0..3  (N)
    const int m0   = blockIdx.y * TM;
    const int n0   = blockIdx.x * TN;

    // cp.async slices.  A tiles: 2048 16B-chunks (4/thread); B tiles: 1024 (2/thread).
    int arow_c[4], achk_c[4];
    uint32_t asw_c[4];
#pragma unroll
    for (int i = 0; i < 4; i++) {
        int e = tid + 512 * i;
        arow_c[i] = e >> 3;             // 0..255
        achk_c[i] = e & 7;
        asw_c[i] = sw128((uint32_t)arow_c[i] * 128u + (uint32_t)achk_c[i] * 16u);
    }
    int brow_c[2], bchk_c[2];
    uint32_t bsw_c[2];
#pragma unroll
    for (int i = 0; i < 2; i++) {
        int e = tid + 512 * i;
        brow_c[i] = e >> 3;             // 0..127
        bchk_c[i] = e & 7;
        bsw_c[i] = sw128((uint32_t)brow_c[i] * 128u + (uint32_t)bchk_c[i] * 16u);
    }

    auto loadChunk = [&](int ch, int buf) {
        const int kk = ch * BK;
        const uint32_t st = sbase + buf * STAGE_B;
#pragma unroll
        for (int i = 0; i < 4; i++) {
            const size_t ga = (size_t)(m0 + arow_c[i]) * GK + kk + achk_c[i] * 8;
            cp16(st + asw_c[i],            g_a_hi + ga);
            cp16(st + TILE_A_B + asw_c[i], g_a_lo + ga);
        }
#pragma unroll
        for (int i = 0; i < 2; i++) {
            const size_t gb = (size_t)(n0 + brow_c[i]) * GK + kk + bchk_c[i] * 8;
            cp16(st + 2 * TILE_A_B + bsw_c[i],            g_b_hi + gb);
            cp16(st + 2 * TILE_A_B + TILE_B_B + bsw_c[i], g_b_lo + gb);
        }
        cp_commit();
    };

    float acc[4][4][4];
#pragma unroll
    for (int mi = 0; mi < 4; mi++)
#pragma unroll
        for (int ni = 0; ni < 4; ni++)
#pragma unroll
            for (int j = 0; j < 4; j++) acc[mi][ni][j] = 0.0f;

    // ldmatrix lane addressing (non-trans for both operands; NT, K-contig)
    const int arow = wm * 64 + (lane & 15);               // + mi*16
    const uint32_t acolb = (uint32_t)((lane >> 4) << 4);
    const int brow = wn * 32 + ((lane >> 4) << 3) + (lane & 7);  // + nb*16
    const uint32_t bcolb = (uint32_t)(((lane >> 3) & 1) << 4);

    loadChunk(0, 0);

    int buf = 0;
    for (int ch = 0; ch < NCHUNK; ch++) {
        if (ch + 1 < NCHUNK) loadChunk(ch + 1, buf ^ 1);

        if (ch + 1 < NCHUNK) cp_wait<1>(); else cp_wait<0>();
        __syncthreads();

        const uint32_t st   = sbase + buf * STAGE_B;
        const uint32_t sAhi = st;
        const uint32_t sAlo = st + TILE_A_B;
        const uint32_t sBhi = st + 2 * TILE_A_B;
        const uint32_t sBlo = st + 2 * TILE_A_B + TILE_B_B;

#pragma unroll
        for (int ks = 0; ks < 4; ks++) {
            const uint32_t kb = (uint32_t)(ks * 32);

            uint32_t Ah[4][4], Al[4][4];
#pragma unroll
            for (int mi = 0; mi < 4; mi++) {
                uint32_t off = (uint32_t)(arow + mi * 16) * 128u + kb + acolb;
                uint32_t sw  = sw128(off);
                ldsm4(Ah[mi][0], Ah[mi][1], Ah[mi][2], Ah[mi][3], sAhi + sw);
                ldsm4(Al[mi][0], Al[mi][1], Al[mi][2], Al[mi][3], sAlo + sw);
            }
            uint32_t Bh[2][4], Bl[2][4];
#pragma unroll
            for (int nb = 0; nb < 2; nb++) {
                uint32_t off = (uint32_t)(brow + nb * 16) * 128u + kb + bcolb;
                uint32_t sw  = sw128(off);
                ldsm4(Bh[nb][0], Bh[nb][1], Bh[nb][2], Bh[nb][3], sBhi + sw);
                ldsm4(Bl[nb][0], Bl[nb][1], Bl[nb][2], Bl[nb][3], sBlo + sw);
            }

#pragma unroll
            for (int mi = 0; mi < 4; mi++)
#pragma unroll
                for (int ni = 0; ni < 4; ni++) {
                    const int nb = ni >> 1, j = ni & 1;
                    uint32_t bh[2] = {Bh[nb][2 * j], Bh[nb][2 * j + 1]};
                    uint32_t bl[2] = {Bl[nb][2 * j], Bl[nb][2 * j + 1]};
                    mma16816(acc[mi][ni], Ah[mi], bh);   // hi*hi
                    mma16816(acc[mi][ni], Ah[mi], bl);   // hi*lo
                    mma16816(acc[mi][ni], Al[mi], bh);   // lo*hi
                }
        }
        __syncthreads();
        buf ^= 1;
    }

    // write V  (D frag: d0,d1 = row lane/4, cols (lane%4)*2,+1; d2,d3 = row+8)
#pragma unroll
    for (int mi = 0; mi < 4; mi++) {
        const int r0 = m0 + wm * 64 + mi * 16 + (lane >> 2);
#pragma unroll
        for (int ni = 0; ni < 4; ni++) {
            const int cc = n0 + wn * 32 + ni * 8 + (lane & 3) * 2;
            float2 v0 = {acc[mi][ni][0], acc[mi][ni][1]};
            float2 v1 = {acc[mi][ni][2], acc[mi][ni][3]};
            *(float2*)&g_v[(size_t)r0 * Nsz + cc]       = v0;
            *(float2*)&g_v[(size_t)(r0 + 8) * Nsz + cc] = v1;
        }
    }
}

// ---------------------------------------------------------------------------
// Kernel 3: epilogue — per-row gate LN, gate math, cell LN.  1 block/row.
// ---------------------------------------------------------------------------
__device__ __forceinline__ float sigf(float v) { return 1.0f / (1.0f + expf(-v)); }

__global__ __launch_bounds__(256) void lstm_epilogue(
    const float* __restrict__ c,
    const float* __restrict__ b_ih,
    const float* __restrict__ gamma_ifgo, const float* __restrict__ beta_ifgo,
    const float* __restrict__ gamma_c,    const float* __restrict__ beta_c,
    float* __restrict__ out)   // [2, B, H]: new_h then new_c
{
    const int b   = blockIdx.x;
    const int tid = threadIdx.x;
    const int col = tid * 4;
    const int lane = tid & 31, wid = tid >> 5;

    const float* vrow = g_v + (size_t)b * Nsz;
    __shared__ float wred[8][8];

    float gv[4][4];
    float s[8];
#pragma unroll
    for (int g = 0; g < 4; g++) {
        float4 t  = *(const float4*)&vrow[g * Hsz + col];
        float4 bb = *(const float4*)&b_ih[g * Hsz + col];
        float v0 = t.x + bb.x, v1 = t.y + bb.y, v2 = t.z + bb.z, v3 = t.w + bb.w;
        gv[g][0] = v0; gv[g][1] = v1; gv[g][2] = v2; gv[g][3] = v3;
        s[2 * g]     = v0 + v1 + v2 + v3;
        s[2 * g + 1] = v0 * v0 + v1 * v1 + v2 * v2 + v3 * v3;
    }

#pragma unroll
    for (int j = 0; j < 8; j++)
#pragma unroll
        for (int off = 16; off > 0; off >>= 1)
            s[j] += __shfl_xor_sync(0xffffffffu, s[j], off);
    if (lane == 0)
#pragma unroll
        for (int j = 0; j < 8; j++) wred[wid][j] = s[j];
    __syncthreads();

    float tot[8];
#pragma unroll
    for (int j = 0; j < 8; j++) {
        float a = 0.0f;
#pragma unroll
        for (int w = 0; w < 8; w++) a += wred[w][j];
        tot[j] = a;
    }

    float ln[4][4];
#pragma unroll
    for (int g = 0; g < 4; g++) {
        float mean = tot[2 * g] * (1.0f / Hsz);
        float var  = (tot[2 * g + 1] - tot[2 * g] * mean) * (1.0f / (Hsz - 1));
        float inv  = 1.0f / (sqrtf(fmaxf(var, 0.0f)) + EPS);
        float4 ga = *(const float4*)&gamma_ifgo[g * Hsz + col];
        float4 be = *(const float4*)&beta_ifgo[g * Hsz + col];
        float gaa[4] = {ga.x, ga.y, ga.z, ga.w};
        float bea[4] = {be.x, be.y, be.z, be.w};
#pragma unroll
        for (int j = 0; j < 4; j++)
            ln[g][j] = gaa[j] * (gv[g][j] - mean) * inv + bea[j];
    }

    float4 cv4 = *(const float4*)&c[(size_t)b * Hsz + col];
    float cva[4] = {cv4.x, cv4.y, cv4.z, cv4.w};
    float nc[4];
    float s2 = 0.0f, s3 = 0.0f;
#pragma unroll
    for (int j = 0; j < 4; j++) {
        float fi = ln[1][j] + 1.0f;
        float v  = cva[j] * sigf(fi) + sigf(ln[0][j]) * tanhf(ln[2][j]);
        nc[j] = v;
        s2 += v;
        s3 += v * v;
    }

    __syncthreads();
#pragma unroll
    for (int off = 16; off > 0; off >>= 1) {
        s2 += __shfl_xor_sync(0xffffffffu, s2, off);
        s3 += __shfl_xor_sync(0xffffffffu, s3, off);
    }
    if (lane == 0) { wred[wid][0] = s2; wred[wid][1] = s3; }
    __syncthreads();
    float t2 = 0.0f, t3 = 0.0f;
#pragma unroll
    for (int w = 0; w < 8; w++) { t2 += wred[w][0]; t3 += wred[w][1]; }

    float mean2 = t2 * (1.0f / Hsz);
    float var2  = (t3 - t2 * mean2) * (1.0f / (Hsz - 1));
    float inv2  = 1.0f / (sqrtf(fmaxf(var2, 0.0f)) + EPS);

    float4 gc4 = *(const float4*)&gamma_c[col];
    float4 bc4 = *(const float4*)&beta_c[col];
    float gca[4] = {gc4.x, gc4.y, gc4.z, gc4.w};
    float bca[4] = {bc4.x, bc4.y, bc4.z, bc4.w};

    float hn[4], cn[4];
#pragma unroll
    for (int j = 0; j < 4; j++) {
        float cl = gca[j] * (nc[j] - mean2) * inv2 + bca[j];
        cn[j] = cl;
        hn[j] = tanhf(cl) * sigf(ln[3][j]);
    }

    float4 ho = {hn[0], hn[1], hn[2], hn[3]};
    float4 co = {cn[0], cn[1], cn[2], cn[3]};
    *(float4*)&out[(size_t)b * Hsz + col]                     = ho;
    *(float4*)&out[(size_t)Bsz * Hsz + (size_t)b * Hsz + col] = co;
}

// ---------------------------------------------------------------------------
// Launch
// ---------------------------------------------------------------------------
extern "C" void kernel_launch(void* const* d_in, const int* in_sizes, int n_in,
                              void* d_out, int out_size)
{
    const float* x          = (const float*)d_in[0];
    const float* h          = (const float*)d_in[1];
    const float* c          = (const float*)d_in[2];
    const float* w_ih       = (const float*)d_in[3];
    const float* b_ih       = (const float*)d_in[4];
    const float* w_hh       = (const float*)d_in[5];
    const float* gamma_ifgo = (const float*)d_in[6];
    const float* beta_ifgo  = (const float*)d_in[7];
    const float* gamma_c    = (const float*)d_in[8];
    const float* beta_c     = (const float*)d_in[9];
    float* out = (float*)d_out;

    // idempotent, called every launch (no static guards)
    cudaFuncSetAttribute(lstm_gemm_mma,
                         cudaFuncAttributeMaxDynamicSharedMemorySize, DYN_SMEM);

    {   // convert: (8192 + 4096) * 512 float4-groups
        size_t groups = ((size_t)Bsz + Nsz) * (GK / 4);
        int blocks = (int)((groups + 255) / 256);
        lstm_convert<<<blocks, 256>>>(x, h, w_ih, w_hh);
    }

    dim3 gemmGrid(Nsz / TN, Bsz / TM);   // (32, 32)
    lstm_gemm_mma<<<gemmGrid, 512, DYN_SMEM>>>();

    lstm_epilogue<<<Bsz, 256>>>(c, b_ih, gamma_ifgo, beta_ifgo,
                                gamma_c, beta_c, out);
}

// round 8
// speedup vs baseline: 2.2672x; 2.2492x over previous
#include <cuda_runtime.h>
#include <cuda_fp16.h>
#include <math.h>
#include <cstdint>

// ---------------------------------------------------------------------------
// LSTMCell, B=8192, In=H=1024.
//   V = [x|h] @ [w_ih|w_hh]^T            (8192x2048 @ 2048x4096^T, NT)
//   gates = LN_per_gate(V + b_ih); f+=1
//   new_c = LN_c(c*sig(f) + sig(i)*tanh(g)); new_h = tanh(new_c)*sig(o)
//
// GEMM bottleneck is legacy-HMMA *issue rate* (R5 memory cut was neutral).
// Single fp16 MMA/kstep (vs split-bf16 3 MMAs): 3x fewer HMMA, 2x less
// operand traffic.  Calibrated error model predicts rel_err ~3e-4.
// (Resubmission of R6/R7 kernel — both benches were infra flakes.)
// ---------------------------------------------------------------------------

#define Bsz   8192
#define Hsz   1024
#define Nsz   4096
#define GK    2048          // packed K = In + H
#define EPS   1e-6f

#define TM    256
#define TN    128
#define BK    64            // K elems per smem chunk (64 fp16 = 128 B row)
#define NCHUNK (GK / BK)    // 32

// per stage: A 256x128B = 32 KB, B 128x128B = 16 KB
#define TILE_A_B 32768
#define TILE_B_B 16384
#define STAGE_B  (TILE_A_B + TILE_B_B)   // 48 KB
#define DYN_SMEM (2 * STAGE_B)           // 96 KB

// ---- scratch (static device globals; allocation-free) ----
__device__ __half g_a[(size_t)Bsz * GK];   // [x|h]       fp16
__device__ __half g_b[(size_t)Nsz * GK];   // [w_ih|w_hh] fp16
__device__ float  g_v[(size_t)Bsz * Nsz];  // pre-activation gates

// ---------------------------------------------------------------------------
// helpers
// ---------------------------------------------------------------------------
__device__ __forceinline__ uint32_t smem_u32(const void* p) {
    uint32_t a;
    asm("{ .reg .u64 t; cvta.to.shared.u64 t, %1; cvt.u32.u64 %0, t; }"
        : "=r"(a) : "l"(p));
    return a;
}
__device__ __forceinline__ uint32_t sw128(uint32_t off) {
    return off ^ ((off >> 3) & 0x70);
}
__device__ __forceinline__ void cp16(uint32_t saddr, const void* gaddr) {
    asm volatile("cp.async.cg.shared.global [%0], [%1], 16;"
                 :: "r"(saddr), "l"(gaddr));
}
__device__ __forceinline__ void cp_commit() {
    asm volatile("cp.async.commit_group;" ::: "memory");
}
template <int N>
__device__ __forceinline__ void cp_wait() {
    asm volatile("cp.async.wait_group %0;" :: "n"(N) : "memory");
}
__device__ __forceinline__ void ldsm4(uint32_t& r0, uint32_t& r1,
                                      uint32_t& r2, uint32_t& r3, uint32_t a) {
    asm volatile("ldmatrix.sync.aligned.m8n8.x4.shared.b16 {%0,%1,%2,%3}, [%4];"
                 : "=r"(r0), "=r"(r1), "=r"(r2), "=r"(r3) : "r"(a));
}
__device__ __forceinline__ void mma16816(float* c, const uint32_t* a,
                                         const uint32_t* b) {
    asm volatile(
        "mma.sync.aligned.m16n8k16.row.col.f32.f16.f16.f32 "
        "{%0,%1,%2,%3}, {%4,%5,%6,%7}, {%8,%9}, {%0,%1,%2,%3};"
        : "+f"(c[0]), "+f"(c[1]), "+f"(c[2]), "+f"(c[3])
        : "r"(a[0]), "r"(a[1]), "r"(a[2]), "r"(a[3]), "r"(b[0]), "r"(b[1]));
}

// ---------------------------------------------------------------------------
// Kernel 1: fp32 -> fp16 into packed [.,2048] scratch
// ---------------------------------------------------------------------------
__global__ __launch_bounds__(256) void lstm_convert(
    const float* __restrict__ x, const float* __restrict__ h,
    const float* __restrict__ w_ih, const float* __restrict__ w_hh)
{
    const size_t NG_A = (size_t)Bsz * (GK / 4);
    const size_t NG   = NG_A + (size_t)Nsz * (GK / 4);
    size_t g = (size_t)blockIdx.x * blockDim.x + threadIdx.x;
    if (g >= NG) return;

    const float* src;
    __half* dst;
    size_t dstoff;
    if (g < NG_A) {
        size_t r = g / (GK / 4);
        int    k = (int)(g % (GK / 4)) * 4;
        src = (k < 1024) ? (x + r * 1024 + k) : (h + r * 1024 + (k - 1024));
        dstoff = r * GK + k;
        dst = g_a;
    } else {
        size_t gb = g - NG_A;
        size_t r = gb / (GK / 4);
        int    k = (int)(gb % (GK / 4)) * 4;
        src = (k < 1024) ? (w_ih + r * 1024 + k) : (w_hh + r * 1024 + (k - 1024));
        dstoff = r * GK + k;
        dst = g_b;
    }

    float4 v = *(const float4*)src;
    __half2 p0 = __floats2half2_rn(v.x, v.y);
    __half2 p1 = __floats2half2_rn(v.z, v.w);
    *(__half2*)(dst + dstoff)     = p0;
    *(__half2*)(dst + dstoff + 2) = p1;
}

// ---------------------------------------------------------------------------
// Kernel 2: fp16 GEMM.  Tile 256x128xBK64, 512 threads,
// 16 warps (4 M x 4 N), warp tile 64x32, double-buffered cp.async.
// ---------------------------------------------------------------------------
__global__ __launch_bounds__(512, 1) void lstm_gemm_mma()
{
    extern __shared__ char smem[];
    const uint32_t sbase = smem_u32(smem);

    const int tid  = threadIdx.x;
    const int lane = tid & 31;
    const int wid  = tid >> 5;
    const int wm   = wid >> 2;          // 0..3  (M)
    const int wn   = wid & 3;           // 0..3  (N)
    const int m0   = blockIdx.y * TM;
    const int n0   = blockIdx.x * TN;

    // cp.async slices.  A tile: 2048 16B-chunks (4/thread); B tile: 1024 (2/thread).
    int arow_c[4], achk_c[4];
    uint32_t asw_c[4];
#pragma unroll
    for (int i = 0; i < 4; i++) {
        int e = tid + 512 * i;
        arow_c[i] = e >> 3;             // 0..255
        achk_c[i] = e & 7;
        asw_c[i] = sw128((uint32_t)arow_c[i] * 128u + (uint32_t)achk_c[i] * 16u);
    }
    int brow_c[2], bchk_c[2];
    uint32_t bsw_c[2];
#pragma unroll
    for (int i = 0; i < 2; i++) {
        int e = tid + 512 * i;
        brow_c[i] = e >> 3;             // 0..127
        bchk_c[i] = e & 7;
        bsw_c[i] = sw128((uint32_t)brow_c[i] * 128u + (uint32_t)bchk_c[i] * 16u);
    }

    auto loadChunk = [&](int ch, int buf) {
        const int kk = ch * BK;
        const uint32_t st = sbase + buf * STAGE_B;
#pragma unroll
        for (int i = 0; i < 4; i++) {
            const size_t ga = (size_t)(m0 + arow_c[i]) * GK + kk + achk_c[i] * 8;
            cp16(st + asw_c[i], g_a + ga);
        }
#pragma unroll
        for (int i = 0; i < 2; i++) {
            const size_t gb = (size_t)(n0 + brow_c[i]) * GK + kk + bchk_c[i] * 8;
            cp16(st + TILE_A_B + bsw_c[i], g_b + gb);
        }
        cp_commit();
    };

    float acc[4][4][4];
#pragma unroll
    for (int mi = 0; mi < 4; mi++)
#pragma unroll
        for (int ni = 0; ni < 4; ni++)
#pragma unroll
            for (int j = 0; j < 4; j++) acc[mi][ni][j] = 0.0f;

    // ldmatrix lane addressing (non-trans for both operands; NT, K-contig)
    const int arow = wm * 64 + (lane & 15);               // + mi*16
    const uint32_t acolb = (uint32_t)((lane >> 4) << 4);
    const int brow = wn * 32 + ((lane >> 4) << 3) + (lane & 7);  // + nb*16
    const uint32_t bcolb = (uint32_t)(((lane >> 3) & 1) << 4);

    loadChunk(0, 0);

    int buf = 0;
    for (int ch = 0; ch < NCHUNK; ch++) {
        if (ch + 1 < NCHUNK) loadChunk(ch + 1, buf ^ 1);

        if (ch + 1 < NCHUNK) cp_wait<1>(); else cp_wait<0>();
        __syncthreads();

        const uint32_t sA = sbase + buf * STAGE_B;
        const uint32_t sB = sA + TILE_A_B;

#pragma unroll
        for (int ks = 0; ks < 4; ks++) {
            const uint32_t kb = (uint32_t)(ks * 32);

            uint32_t Af[4][4];
#pragma unroll
            for (int mi = 0; mi < 4; mi++) {
                uint32_t off = (uint32_t)(arow + mi * 16) * 128u + kb + acolb;
                ldsm4(Af[mi][0], Af[mi][1], Af[mi][2], Af[mi][3], sA + sw128(off));
            }
            uint32_t Bf[2][4];
#pragma unroll
            for (int nb = 0; nb < 2; nb++) {
                uint32_t off = (uint32_t)(brow + nb * 16) * 128u + kb + bcolb;
                ldsm4(Bf[nb][0], Bf[nb][1], Bf[nb][2], Bf[nb][3], sB + sw128(off));
            }

#pragma unroll
            for (int mi = 0; mi < 4; mi++)
#pragma unroll
                for (int ni = 0; ni < 4; ni++) {
                    const int nb = ni >> 1, j = ni & 1;
                    uint32_t bb[2] = {Bf[nb][2 * j], Bf[nb][2 * j + 1]};
                    mma16816(acc[mi][ni], Af[mi], bb);
                }
        }
        __syncthreads();
        buf ^= 1;
    }

    // write V  (D frag: d0,d1 = row lane/4, cols (lane%4)*2,+1; d2,d3 = row+8)
#pragma unroll
    for (int mi = 0; mi < 4; mi++) {
        const int r0 = m0 + wm * 64 + mi * 16 + (lane >> 2);
#pragma unroll
        for (int ni = 0; ni < 4; ni++) {
            const int cc = n0 + wn * 32 + ni * 8 + (lane & 3) * 2;
            float2 v0 = {acc[mi][ni][0], acc[mi][ni][1]};
            float2 v1 = {acc[mi][ni][2], acc[mi][ni][3]};
            *(float2*)&g_v[(size_t)r0 * Nsz + cc]       = v0;
            *(float2*)&g_v[(size_t)(r0 + 8) * Nsz + cc] = v1;
        }
    }
}

// ---------------------------------------------------------------------------
// Kernel 3: epilogue — per-row gate LN, gate math, cell LN.  1 block/row.
// ---------------------------------------------------------------------------
__device__ __forceinline__ float sigf(float v) { return 1.0f / (1.0f + expf(-v)); }

__global__ __launch_bounds__(256) void lstm_epilogue(
    const float* __restrict__ c,
    const float* __restrict__ b_ih,
    const float* __restrict__ gamma_ifgo, const float* __restrict__ beta_ifgo,
    const float* __restrict__ gamma_c,    const float* __restrict__ beta_c,
    float* __restrict__ out)   // [2, B, H]: new_h then new_c
{
    const int b   = blockIdx.x;
    const int tid = threadIdx.x;
    const int col = tid * 4;
    const int lane = tid & 31, wid = tid >> 5;

    const float* vrow = g_v + (size_t)b * Nsz;
    __shared__ float wred[8][8];

    float gv[4][4];
    float s[8];
#pragma unroll
    for (int g = 0; g < 4; g++) {
        float4 t  = *(const float4*)&vrow[g * Hsz + col];
        float4 bb = *(const float4*)&b_ih[g * Hsz + col];
        float v0 = t.x + bb.x, v1 = t.y + bb.y, v2 = t.z + bb.z, v3 = t.w + bb.w;
        gv[g][0] = v0; gv[g][1] = v1; gv[g][2] = v2; gv[g][3] = v3;
        s[2 * g]     = v0 + v1 + v2 + v3;
        s[2 * g + 1] = v0 * v0 + v1 * v1 + v2 * v2 + v3 * v3;
    }

#pragma unroll
    for (int j = 0; j < 8; j++)
#pragma unroll
        for (int off = 16; off > 0; off >>= 1)
            s[j] += __shfl_xor_sync(0xffffffffu, s[j], off);
    if (lane == 0)
#pragma unroll
        for (int j = 0; j < 8; j++) wred[wid][j] = s[j];
    __syncthreads();

    float tot[8];
#pragma unroll
    for (int j = 0; j < 8; j++) {
        float a = 0.0f;
#pragma unroll
        for (int w = 0; w < 8; w++) a += wred[w][j];
        tot[j] = a;
    }

    float ln[4][4];
#pragma unroll
    for (int g = 0; g < 4; g++) {
        float mean = tot[2 * g] * (1.0f / Hsz);
        float var  = (tot[2 * g + 1] - tot[2 * g] * mean) * (1.0f / (Hsz - 1));
        float inv  = 1.0f / (sqrtf(fmaxf(var, 0.0f)) + EPS);
        float4 ga = *(const float4*)&gamma_ifgo[g * Hsz + col];
        float4 be = *(const float4*)&beta_ifgo[g * Hsz + col];
        float gaa[4] = {ga.x, ga.y, ga.z, ga.w};
        float bea[4] = {be.x, be.y, be.z, be.w};
#pragma unroll
        for (int j = 0; j < 4; j++)
            ln[g][j] = gaa[j] * (gv[g][j] - mean) * inv + bea[j];
    }

    float4 cv4 = *(const float4*)&c[(size_t)b * Hsz + col];
    float cva[4] = {cv4.x, cv4.y, cv4.z, cv4.w};
    float nc[4];
    float s2 = 0.0f, s3 = 0.0f;
#pragma unroll
    for (int j = 0; j < 4; j++) {
        float fi = ln[1][j] + 1.0f;
        float v  = cva[j] * sigf(fi) + sigf(ln[0][j]) * tanhf(ln[2][j]);
        nc[j] = v;
        s2 += v;
        s3 += v * v;
    }

    __syncthreads();
#pragma unroll
    for (int off = 16; off > 0; off >>= 1) {
        s2 += __shfl_xor_sync(0xffffffffu, s2, off);
        s3 += __shfl_xor_sync(0xffffffffu, s3, off);
    }
    if (lane == 0) { wred[wid][0] = s2; wred[wid][1] = s3; }
    __syncthreads();
    float t2 = 0.0f, t3 = 0.0f;
#pragma unroll
    for (int w = 0; w < 8; w++) { t2 += wred[w][0]; t3 += wred[w][1]; }

    float mean2 = t2 * (1.0f / Hsz);
    float var2  = (t3 - t2 * mean2) * (1.0f / (Hsz - 1));
    float inv2  = 1.0f / (sqrtf(fmaxf(var2, 0.0f)) + EPS);

    float4 gc4 = *(const float4*)&gamma_c[col];
    float4 bc4 = *(const float4*)&beta_c[col];
    float gca[4] = {gc4.x, gc4.y, gc4.z, gc4.w};
    float bca[4] = {bc4.x, bc4.y, bc4.z, bc4.w};

    float hn[4], cn[4];
#pragma unroll
    for (int j = 0; j < 4; j++) {
        float cl = gca[j] * (nc[j] - mean2) * inv2 + bca[j];
        cn[j] = cl;
        hn[j] = tanhf(cl) * sigf(ln[3][j]);
    }

    float4 ho = {hn[0], hn[1], hn[2], hn[3]};
    float4 co = {cn[0], cn[1], cn[2], cn[3]};
    *(float4*)&out[(size_t)b * Hsz + col]                     = ho;
    *(float4*)&out[(size_t)Bsz * Hsz + (size_t)b * Hsz + col] = co;
}

// ---------------------------------------------------------------------------
// Launch
// ---------------------------------------------------------------------------
extern "C" void kernel_launch(void* const* d_in, const int* in_sizes, int n_in,
                              void* d_out, int out_size)
{
    const float* x          = (const float*)d_in[0];
    const float* h          = (const float*)d_in[1];
    const float* c          = (const float*)d_in[2];
    const float* w_ih       = (const float*)d_in[3];
    const float* b_ih       = (const float*)d_in[4];
    const float* w_hh       = (const float*)d_in[5];
    const float* gamma_ifgo = (const float*)d_in[6];
    const float* beta_ifgo  = (const float*)d_in[7];
    const float* gamma_c    = (const float*)d_in[8];
    const float* beta_c     = (const float*)d_in[9];
    float* out = (float*)d_out;

    // idempotent, called every launch (no static guards)
    cudaFuncSetAttribute(lstm_gemm_mma,
                         cudaFuncAttributeMaxDynamicSharedMemorySize, DYN_SMEM);

    {   // convert: (8192 + 4096) * 512 float4-groups
        size_t groups = ((size_t)Bsz + Nsz) * (GK / 4);
        int blocks = (int)((groups + 255) / 256);
        lstm_convert<<<blocks, 256>>>(x, h, w_ih, w_hh);
    }

    dim3 gemmGrid(Nsz / TN, Bsz / TM);   // (32, 32)
    lstm_gemm_mma<<<gemmGrid, 512, DYN_SMEM>>>();

    lstm_epilogue<<<Bsz, 256>>>(c, b_ih, gamma_ifgo, beta_ifgo,
                                gamma_c, beta_c, out);
}

// round 10
// speedup vs baseline: 2.3090x; 1.0184x over previous
#include <cuda_runtime.h>
#include <cuda_fp16.h>
#include <math.h>
#include <cstdint>

// ---------------------------------------------------------------------------
// LSTMCell, B=8192, In=H=1024.
//   V = [x|h] @ [w_ih|w_hh]^T            (8192x2048 @ 2048x4096^T, NT)
//   gates = LN_per_gate(V + b_ih); f+=1
//   new_c = LN_c(c*sig(f) + sig(i)*tanh(g)); new_h = tanh(new_c)*sig(o)
//
// R8 (465 us, rel_err 2.08e-4): fp16 single-MMA GEMM, HMMA-pipe bound.
// R9/R10: 3-stage cp.async pipeline (was 2) so the per-chunk wait targets
// a group issued 2 iterations back (always complete) instead of 1 (in
// flight).  GEMM arithmetic unchanged -> rel_err must stay 2.081e-4.
// (R10 = byte-identical resubmission of R9; R9 bench was an infra flake.)
// ---------------------------------------------------------------------------

#define Bsz   8192
#define Hsz   1024
#define Nsz   4096
#define GK    2048          // packed K = In + H
#define EPS   1e-6f

#define TM    256
#define TN    128
#define BK    64            // K elems per smem chunk (64 fp16 = 128 B row)
#define NCHUNK (GK / BK)    // 32
#define NSTAGE 3

// per stage: A 256x128B = 32 KB, B 128x128B = 16 KB
#define TILE_A_B 32768
#define TILE_B_B 16384
#define STAGE_B  (TILE_A_B + TILE_B_B)   // 48 KB
#define DYN_SMEM (NSTAGE * STAGE_B)      // 144 KB

// ---- scratch (static device globals; allocation-free) ----
__device__ __half g_a[(size_t)Bsz * GK];   // [x|h]       fp16
__device__ __half g_b[(size_t)Nsz * GK];   // [w_ih|w_hh] fp16
__device__ float  g_v[(size_t)Bsz * Nsz];  // pre-activation gates

// ---------------------------------------------------------------------------
// helpers
// ---------------------------------------------------------------------------
__device__ __forceinline__ uint32_t smem_u32(const void* p) {
    uint32_t a;
    asm("{ .reg .u64 t; cvta.to.shared.u64 t, %1; cvt.u32.u64 %0, t; }"
        : "=r"(a) : "l"(p));
    return a;
}
__device__ __forceinline__ uint32_t sw128(uint32_t off) {
    return off ^ ((off >> 3) & 0x70);
}
__device__ __forceinline__ void cp16(uint32_t saddr, const void* gaddr) {
    asm volatile("cp.async.cg.shared.global [%0], [%1], 16;"
                 :: "r"(saddr), "l"(gaddr));
}
__device__ __forceinline__ void cp_commit() {
    asm volatile("cp.async.commit_group;" ::: "memory");
}
template <int N>
__device__ __forceinline__ void cp_wait() {
    asm volatile("cp.async.wait_group %0;" :: "n"(N) : "memory");
}
__device__ __forceinline__ void ldsm4(uint32_t& r0, uint32_t& r1,
                                      uint32_t& r2, uint32_t& r3, uint32_t a) {
    asm volatile("ldmatrix.sync.aligned.m8n8.x4.shared.b16 {%0,%1,%2,%3}, [%4];"
                 : "=r"(r0), "=r"(r1), "=r"(r2), "=r"(r3) : "r"(a));
}
__device__ __forceinline__ void mma16816(float* c, const uint32_t* a,
                                         const uint32_t* b) {
    asm volatile(
        "mma.sync.aligned.m16n8k16.row.col.f32.f16.f16.f32 "
        "{%0,%1,%2,%3}, {%4,%5,%6,%7}, {%8,%9}, {%0,%1,%2,%3};"
        : "+f"(c[0]), "+f"(c[1]), "+f"(c[2]), "+f"(c[3])
        : "r"(a[0]), "r"(a[1]), "r"(a[2]), "r"(a[3]), "r"(b[0]), "r"(b[1]));
}

// ---------------------------------------------------------------------------
// Kernel 1: fp32 -> fp16 into packed [.,2048] scratch
// ---------------------------------------------------------------------------
__global__ __launch_bounds__(256) void lstm_convert(
    const float* __restrict__ x, const float* __restrict__ h,
    const float* __restrict__ w_ih, const float* __restrict__ w_hh)
{
    const size_t NG_A = (size_t)Bsz * (GK / 4);
    const size_t NG   = NG_A + (size_t)Nsz * (GK / 4);
    size_t g = (size_t)blockIdx.x * blockDim.x + threadIdx.x;
    if (g >= NG) return;

    const float* src;
    __half* dst;
    size_t dstoff;
    if (g < NG_A) {
        size_t r = g / (GK / 4);
        int    k = (int)(g % (GK / 4)) * 4;
        src = (k < 1024) ? (x + r * 1024 + k) : (h + r * 1024 + (k - 1024));
        dstoff = r * GK + k;
        dst = g_a;
    } else {
        size_t gb = g - NG_A;
        size_t r = gb / (GK / 4);
        int    k = (int)(gb % (GK / 4)) * 4;
        src = (k < 1024) ? (w_ih + r * 1024 + k) : (w_hh + r * 1024 + (k - 1024));
        dstoff = r * GK + k;
        dst = g_b;
    }

    float4 v = *(const float4*)src;
    __half2 p0 = __floats2half2_rn(v.x, v.y);
    __half2 p1 = __floats2half2_rn(v.z, v.w);
    *(__half2*)(dst + dstoff)     = p0;
    *(__half2*)(dst + dstoff + 2) = p1;
}

// ---------------------------------------------------------------------------
// Kernel 2: fp16 GEMM.  Tile 256x128xBK64, 512 threads,
// 16 warps (4 M x 4 N), warp tile 64x32, 3-stage cp.async pipeline.
// ---------------------------------------------------------------------------
__global__ __launch_bounds__(512, 1) void lstm_gemm_mma()
{
    extern __shared__ char smem[];
    const uint32_t sbase = smem_u32(smem);

    const int tid  = threadIdx.x;
    const int lane = tid & 31;
    const int wid  = tid >> 5;
    const int wm   = wid >> 2;          // 0..3  (M)
    const int wn   = wid & 3;           // 0..3  (N)
    const int m0   = blockIdx.y * TM;
    const int n0   = blockIdx.x * TN;

    // cp.async slices.  A tile: 2048 16B-chunks (4/thread); B tile: 1024 (2/thread).
    int arow_c[4], achk_c[4];
    uint32_t asw_c[4];
#pragma unroll
    for (int i = 0; i < 4; i++) {
        int e = tid + 512 * i;
        arow_c[i] = e >> 3;             // 0..255
        achk_c[i] = e & 7;
        asw_c[i] = sw128((uint32_t)arow_c[i] * 128u + (uint32_t)achk_c[i] * 16u);
    }
    int brow_c[2], bchk_c[2];
    uint32_t bsw_c[2];
#pragma unroll
    for (int i = 0; i < 2; i++) {
        int e = tid + 512 * i;
        brow_c[i] = e >> 3;             // 0..127
        bchk_c[i] = e & 7;
        bsw_c[i] = sw128((uint32_t)brow_c[i] * 128u + (uint32_t)bchk_c[i] * 16u);
    }

    auto loadChunk = [&](int ch, int buf) {
        const int kk = ch * BK;
        const uint32_t st = sbase + buf * STAGE_B;
#pragma unroll
        for (int i = 0; i < 4; i++) {
            const size_t ga = (size_t)(m0 + arow_c[i]) * GK + kk + achk_c[i] * 8;
            cp16(st + asw_c[i], g_a + ga);
        }
#pragma unroll
        for (int i = 0; i < 2; i++) {
            const size_t gb = (size_t)(n0 + brow_c[i]) * GK + kk + bchk_c[i] * 8;
            cp16(st + TILE_A_B + bsw_c[i], g_b + gb);
        }
        cp_commit();
    };

    float acc[4][4][4];
#pragma unroll
    for (int mi = 0; mi < 4; mi++)
#pragma unroll
        for (int ni = 0; ni < 4; ni++)
#pragma unroll
            for (int j = 0; j < 4; j++) acc[mi][ni][j] = 0.0f;

    // ldmatrix lane addressing (non-trans for both operands; NT, K-contig)
    const int arow = wm * 64 + (lane & 15);               // + mi*16
    const uint32_t acolb = (uint32_t)((lane >> 4) << 4);
    const int brow = wn * 32 + ((lane >> 4) << 3) + (lane & 7);  // + nb*16
    const uint32_t bcolb = (uint32_t)(((lane >> 3) & 1) << 4);

    // prologue: stages 0 and 1 in flight
    loadChunk(0, 0);
    loadChunk(1, 1);

    for (int ch = 0; ch < NCHUNK; ch++) {
        // Guard: buffer (ch+2)%NSTAGE was last READ during iteration ch-1.
        // This barrier orders that read before the overwrite below.
        __syncthreads();

        if (ch + 2 < NCHUNK) {
            loadChunk(ch + 2, (ch + 2) % NSTAGE);
            cp_wait<2>();        // group(ch) complete; ch+1, ch+2 may pend
        } else if (ch + 1 < NCHUNK) {
            cp_wait<1>();        // group(ch) complete; ch+1 may pend
        } else {
            cp_wait<0>();
        }
        __syncthreads();         // all warps see stage ch data

        const uint32_t sA = sbase + (ch % NSTAGE) * STAGE_B;
        const uint32_t sB = sA + TILE_A_B;

#pragma unroll
        for (int ks = 0; ks < 4; ks++) {
            const uint32_t kb = (uint32_t)(ks * 32);

            uint32_t Af[4][4];
#pragma unroll
            for (int mi = 0; mi < 4; mi++) {
                uint32_t off = (uint32_t)(arow + mi * 16) * 128u + kb + acolb;
                ldsm4(Af[mi][0], Af[mi][1], Af[mi][2], Af[mi][3], sA + sw128(off));
            }
            uint32_t Bf[2][4];
#pragma unroll
            for (int nb = 0; nb < 2; nb++) {
                uint32_t off = (uint32_t)(brow + nb * 16) * 128u + kb + bcolb;
                ldsm4(Bf[nb][0], Bf[nb][1], Bf[nb][2], Bf[nb][3], sB + sw128(off));
            }

#pragma unroll
            for (int mi = 0; mi < 4; mi++)
#pragma unroll
                for (int ni = 0; ni < 4; ni++) {
                    const int nb = ni >> 1, j = ni & 1;
                    uint32_t bb[2] = {Bf[nb][2 * j], Bf[nb][2 * j + 1]};
                    mma16816(acc[mi][ni], Af[mi], bb);
                }
        }
    }

    // write V  (D frag: d0,d1 = row lane/4, cols (lane%4)*2,+1; d2,d3 = row+8)
#pragma unroll
    for (int mi = 0; mi < 4; mi++) {
        const int r0 = m0 + wm * 64 + mi * 16 + (lane >> 2);
#pragma unroll
        for (int ni = 0; ni < 4; ni++) {
            const int cc = n0 + wn * 32 + ni * 8 + (lane & 3) * 2;
            float2 v0 = {acc[mi][ni][0], acc[mi][ni][1]};
            float2 v1 = {acc[mi][ni][2], acc[mi][ni][3]};
            *(float2*)&g_v[(size_t)r0 * Nsz + cc]       = v0;
            *(float2*)&g_v[(size_t)(r0 + 8) * Nsz + cc] = v1;
        }
    }
}

// ---------------------------------------------------------------------------
// Kernel 3: epilogue — per-row gate LN, gate math, cell LN.  1 block/row.
// ---------------------------------------------------------------------------
__device__ __forceinline__ float sigf(float v) { return 1.0f / (1.0f + expf(-v)); }

__global__ __launch_bounds__(256) void lstm_epilogue(
    const float* __restrict__ c,
    const float* __restrict__ b_ih,
    const float* __restrict__ gamma_ifgo, const float* __restrict__ beta_ifgo,
    const float* __restrict__ gamma_c,    const float* __restrict__ beta_c,
    float* __restrict__ out)   // [2, B, H]: new_h then new_c
{
    const int b   = blockIdx.x;
    const int tid = threadIdx.x;
    const int col = tid * 4;
    const int lane = tid & 31, wid = tid >> 5;

    const float* vrow = g_v + (size_t)b * Nsz;
    __shared__ float wred[8][8];

    float gv[4][4];
    float s[8];
#pragma unroll
    for (int g = 0; g < 4; g++) {
        float4 t  = *(const float4*)&vrow[g * Hsz + col];
        float4 bb = *(const float4*)&b_ih[g * Hsz + col];
        float v0 = t.x + bb.x, v1 = t.y + bb.y, v2 = t.z + bb.z, v3 = t.w + bb.w;
        gv[g][0] = v0; gv[g][1] = v1; gv[g][2] = v2; gv[g][3] = v3;
        s[2 * g]     = v0 + v1 + v2 + v3;
        s[2 * g + 1] = v0 * v0 + v1 * v1 + v2 * v2 + v3 * v3;
    }

#pragma unroll
    for (int j = 0; j < 8; j++)
#pragma unroll
        for (int off = 16; off > 0; off >>= 1)
            s[j] += __shfl_xor_sync(0xffffffffu, s[j], off);
    if (lane == 0)
#pragma unroll
        for (int j = 0; j < 8; j++) wred[wid][j] = s[j];
    __syncthreads();

    float tot[8];
#pragma unroll
    for (int j = 0; j < 8; j++) {
        float a = 0.0f;
#pragma unroll
        for (int w = 0; w < 8; w++) a += wred[w][j];
        tot[j] = a;
    }

    float ln[4][4];
#pragma unroll
    for (int g = 0; g < 4; g++) {
        float mean = tot[2 * g] * (1.0f / Hsz);
        float var  = (tot[2 * g + 1] - tot[2 * g] * mean) * (1.0f / (Hsz - 1));
        float inv  = 1.0f / (sqrtf(fmaxf(var, 0.0f)) + EPS);
        float4 ga = *(const float4*)&gamma_ifgo[g * Hsz + col];
        float4 be = *(const float4*)&beta_ifgo[g * Hsz + col];
        float gaa[4] = {ga.x, ga.y, ga.z, ga.w};
        float bea[4] = {be.x, be.y, be.z, be.w};
#pragma unroll
        for (int j = 0; j < 4; j++)
            ln[g][j] = gaa[j] * (gv[g][j] - mean) * inv + bea[j];
    }

    float4 cv4 = *(const float4*)&c[(size_t)b * Hsz + col];
    float cva[4] = {cv4.x, cv4.y, cv4.z, cv4.w};
    float nc[4];
    float s2 = 0.0f, s3 = 0.0f;
#pragma unroll
    for (int j = 0; j < 4; j++) {
        float fi = ln[1][j] + 1.0f;
        float v  = cva[j] * sigf(fi) + sigf(ln[0][j]) * tanhf(ln[2][j]);
        nc[j] = v;
        s2 += v;
        s3 += v * v;
    }

    __syncthreads();
#pragma unroll
    for (int off = 16; off > 0; off >>= 1) {
        s2 += __shfl_xor_sync(0xffffffffu, s2, off);
        s3 += __shfl_xor_sync(0xffffffffu, s3, off);
    }
    if (lane == 0) { wred[wid][0] = s2; wred[wid][1] = s3; }
    __syncthreads();
    float t2 = 0.0f, t3 = 0.0f;
#pragma unroll
    for (int w = 0; w < 8; w++) { t2 += wred[w][0]; t3 += wred[w][1]; }

    float mean2 = t2 * (1.0f / Hsz);
    float var2  = (t3 - t2 * mean2) * (1.0f / (Hsz - 1));
    float inv2  = 1.0f / (sqrtf(fmaxf(var2, 0.0f)) + EPS);

    float4 gc4 = *(const float4*)&gamma_c[col];
    float4 bc4 = *(const float4*)&beta_c[col];
    float gca[4] = {gc4.x, gc4.y, gc4.z, gc4.w};
    float bca[4] = {bc4.x, bc4.y, bc4.z, bc4.w};

    float hn[4], cn[4];
#pragma unroll
    for (int j = 0; j < 4; j++) {
        float cl = gca[j] * (nc[j] - mean2) * inv2 + bca[j];
        cn[j] = cl;
        hn[j] = tanhf(cl) * sigf(ln[3][j]);
    }

    float4 ho = {hn[0], hn[1], hn[2], hn[3]};
    float4 co = {cn[0], cn[1], cn[2], cn[3]};
    *(float4*)&out[(size_t)b * Hsz + col]                     = ho;
    *(float4*)&out[(size_t)Bsz * Hsz + (size_t)b * Hsz + col] = co;
}

// ---------------------------------------------------------------------------
// Launch
// ---------------------------------------------------------------------------
extern "C" void kernel_launch(void* const* d_in, const int* in_sizes, int n_in,
                              void* d_out, int out_size)
{
    const float* x          = (const float*)d_in[0];
    const float* h          = (const float*)d_in[1];
    const float* c          = (const float*)d_in[2];
    const float* w_ih       = (const float*)d_in[3];
    const float* b_ih       = (const float*)d_in[4];
    const float* w_hh       = (const float*)d_in[5];
    const float* gamma_ifgo = (const float*)d_in[6];
    const float* beta_ifgo  = (const float*)d_in[7];
    const float* gamma_c    = (const float*)d_in[8];
    const float* beta_c     = (const float*)d_in[9];
    float* out = (float*)d_out;

    // idempotent, called every launch (no static guards)
    cudaFuncSetAttribute(lstm_gemm_mma,
                         cudaFuncAttributeMaxDynamicSharedMemorySize, DYN_SMEM);

    {   // convert: (8192 + 4096) * 512 float4-groups
        size_t groups = ((size_t)Bsz + Nsz) * (GK / 4);
        int blocks = (int)((groups + 255) / 256);
        lstm_convert<<<blocks, 256>>>(x, h, w_ih, w_hh);
    }

    dim3 gemmGrid(Nsz / TN, Bsz / TM);   // (32, 32)
    lstm_gemm_mma<<<gemmGrid, 512, DYN_SMEM>>>();

    lstm_epilogue<<<Bsz, 256>>>(c, b_ih, gamma_ifgo, beta_ifgo,
                                gamma_c, beta_c, out);
}